// round 14
// baseline (speedup 1.0000x reference)
#include <cuda_runtime.h>
#include <math.h>
#include <stdint.h>

#define Bsz 16
#define SEQ 1024
#define HID 768
#define FFD 3072
#define NHD 12
#define DHD 64
#define MROWS (Bsz*SEQ)   // 16384
#define HKP (HID/2)       // 384
#define FKP (FFD/2)       // 1536

// ---------------- fp32 scratch ----------------
__device__ float g_q   [(size_t)MROWS*HID];
__device__ float g_k   [(size_t)MROWS*HID];
__device__ float g_v   [(size_t)MROWS*HID];
__device__ float g_attn[(size_t)MROWS*HID];
__device__ float g_tmp [(size_t)MROWS*HID];
__device__ float g_cls [(size_t)Bsz*HID];

// ---------------- split-bf16 scratch ----------------
__device__ uint32_t g_hidH [(size_t)MROWS*HKP];
__device__ uint32_t g_hidL [(size_t)MROWS*HKP];
__device__ uint32_t g_ctxH [(size_t)MROWS*HKP];
__device__ uint32_t g_ctxL [(size_t)MROWS*HKP];
__device__ uint32_t g_attnH[(size_t)MROWS*HKP];
__device__ uint32_t g_attnL[(size_t)MROWS*HKP];
__device__ uint32_t g_ffH  [(size_t)MROWS*FKP];
__device__ uint32_t g_ffL  [(size_t)MROWS*FKP];
__device__ uint32_t g_WqH[HKP*HID], g_WqL[HKP*HID];
__device__ uint32_t g_WkH[HKP*HID], g_WkL[HKP*HID];
__device__ uint32_t g_WvH[HKP*HID], g_WvL[HKP*HID];
__device__ uint32_t g_WoH[HKP*HID], g_WoL[HKP*HID];
__device__ uint32_t g_W1H[HKP*FFD], g_W1L[HKP*FFD];
__device__ uint32_t g_W2H[FKP*HID], g_W2L[FKP*HID];

// ---------------- bf16 split helpers ----------------
__device__ __forceinline__ uint32_t packbf(float lo, float hi) {
    uint32_t r;
    asm("cvt.rn.bf16x2.f32 %0, %1, %2;" : "=r"(r) : "f"(hi), "f"(lo));
    return r;
}
__device__ __forceinline__ float bf_lo(uint32_t u) { return __uint_as_float(u << 16); }
__device__ __forceinline__ float bf_hi(uint32_t u) { return __uint_as_float(u & 0xFFFF0000u); }

__device__ __forceinline__ void mma_bf16(float* c,
                                         const uint32_t* a, uint32_t b0, uint32_t b1)
{
    asm volatile(
        "mma.sync.aligned.m16n8k16.row.col.f32.bf16.bf16.f32 "
        "{%0,%1,%2,%3}, {%4,%5,%6,%7}, {%8,%9}, {%0,%1,%2,%3};\n"
        : "+f"(c[0]), "+f"(c[1]), "+f"(c[2]), "+f"(c[3])
        : "r"(a[0]), "r"(a[1]), "r"(a[2]), "r"(a[3]), "r"(b0), "r"(b1));
}

__device__ __forceinline__ void cp16(uint32_t sm, const void* g) {
    asm volatile("cp.async.cg.shared.global [%0], [%1], 16;" :: "r"(sm), "l"(g));
}

// ---------------- conversion pre-passes ----------------
__global__ void convA_kernel(const float* __restrict__ X,
                             uint32_t* __restrict__ Xh, uint32_t* __restrict__ Xl,
                             size_t n)
{
    size_t i = (size_t)blockIdx.x * blockDim.x + threadIdx.x;
    if (i >= n) return;
    float2 v = ((const float2*)X)[i];
    uint32_t h = packbf(v.x, v.y);
    Xh[i] = h;
    Xl[i] = packbf(v.x - bf_lo(h), v.y - bf_hi(h));
}

__global__ void convB_kernel(const float* __restrict__ W,
                             uint32_t* __restrict__ Wh, uint32_t* __restrict__ Wl,
                             int Kp, int N)
{
    int i = blockIdx.x * blockDim.x + threadIdx.x;
    if (i >= Kp * N) return;
    int kp = i / N, n = i % N;
    float a = W[(size_t)(2 * kp) * N + n];
    float b = W[(size_t)(2 * kp + 1) * N + n];
    uint32_t h = packbf(a, b);
    Wh[i] = h;
    Wl[i] = packbf(a - bf_lo(h), b - bf_hi(h));
}

// ---------------- GEMM body: pre-split operands, cp.async 2-stage --------
// 2 stages (75.8 KB) -> 2 CTAs/SM resident (vs 1 with 3 stages).
#define ASTRIDE 20
#define BSTRIDE 136
#define APLANE (128*ASTRIDE)
#define BPLANE (16*BSTRIDE)
#define STAGEU (2*APLANE + 2*BPLANE)
#define GEMM_SMEM (2*STAGEU*4)

template<int EPI>
__device__ __forceinline__
void gemm_body(const uint32_t* __restrict__ Agh, const uint32_t* __restrict__ Agl,
               const uint32_t* __restrict__ Bgh, const uint32_t* __restrict__ Bgl,
               const float* __restrict__ bias, const float* __restrict__ resid,
               float* __restrict__ C, uint32_t* __restrict__ Ch, uint32_t* __restrict__ Cl,
               int N, int K, int m0, int n0, uint32_t* smx)
{
    const uint32_t smbase = (uint32_t)__cvta_generic_to_shared(smx);
    const int Kp = K >> 1;

    const int tid = threadIdx.x;
    const int wid = tid >> 5;
    const int lane = tid & 31;
    const int gid = lane >> 2;
    const int tig = lane & 3;
    const int warp_m = wid >> 2;
    const int warp_n = wid & 3;

    int am[2], ak[2], bk[2], bn[2];
    #pragma unroll
    for (int L = 0; L < 2; L++) {
        int c = tid + L * 256;
        am[L] = c >> 2;  ak[L] = (c & 3) * 4;
        bk[L] = c >> 5;  bn[L] = (c & 31) * 4;
    }

    auto issue = [&](int kt) {
        uint32_t st = smbase + (uint32_t)(kt & 1) * (STAGEU * 4);
        #pragma unroll
        for (int L = 0; L < 2; L++) {
            size_t ao = (size_t)(m0 + am[L]) * Kp + kt * 16 + ak[L];
            uint32_t ad = st + (am[L] * ASTRIDE + ak[L]) * 4;
            cp16(ad, Agh + ao);
            cp16(ad + APLANE * 4, Agl + ao);
            size_t bo = (size_t)(kt * 16 + bk[L]) * N + n0 + bn[L];
            uint32_t bd = st + (2 * APLANE + bk[L] * BSTRIDE + bn[L]) * 4;
            cp16(bd, Bgh + bo);
            cp16(bd + BPLANE * 4, Bgl + bo);
        }
        asm volatile("cp.async.commit_group;");
    };

    float acc[4][4][4];
    #pragma unroll
    for (int i = 0; i < 4; i++)
        #pragma unroll
        for (int j = 0; j < 4; j++)
            #pragma unroll
            for (int r = 0; r < 4; r++) acc[i][j][r] = 0.f;

    const int NT = K >> 5;
    issue(0);

    for (int kt = 0; kt < NT; kt++) {
        asm volatile("cp.async.wait_group 0;");
        __syncthreads();                      // buffer kt&1 visible; prior compute done
        if (kt + 1 < NT) issue(kt + 1);       // prefetch into other buffer, overlaps compute

        const uint32_t* Sb = smx + (kt & 1) * STAGEU;
        const uint32_t* Bh_s = Sb + 2 * APLANE;
        const uint32_t* Bl_s = Bh_s + BPLANE;

        #pragma unroll
        for (int s = 0; s < 2; s++) {
            const uint32_t* pa = Sb + (warp_m * 64 + gid) * ASTRIDE + s * 8 + tig;
            const uint32_t* pl = pa + APLANE;

            uint32_t ah[4][4], al[4][4];
            #pragma unroll
            for (int mi = 0; mi < 4; mi++) {
                const uint32_t* qq = pa + mi * 16 * ASTRIDE;
                ah[mi][0] = qq[0];
                ah[mi][1] = qq[8 * ASTRIDE];
                ah[mi][2] = qq[4];
                ah[mi][3] = qq[8 * ASTRIDE + 4];
                const uint32_t* rr = pl + mi * 16 * ASTRIDE;
                al[mi][0] = rr[0];
                al[mi][1] = rr[8 * ASTRIDE];
                al[mi][2] = rr[4];
                al[mi][3] = rr[8 * ASTRIDE + 4];
            }
            const uint32_t* pb = Bh_s + (s * 8 + tig) * BSTRIDE + warp_n * 32 + gid;
            const uint32_t* pc = Bl_s + (s * 8 + tig) * BSTRIDE + warp_n * 32 + gid;
            #pragma unroll
            for (int nj = 0; nj < 4; nj++) {
                uint32_t bh0 = pb[nj * 8], bh1 = pb[nj * 8 + 4 * BSTRIDE];
                uint32_t bl0 = pc[nj * 8], bl1 = pc[nj * 8 + 4 * BSTRIDE];
                #pragma unroll
                for (int mi = 0; mi < 4; mi++) {
                    mma_bf16(acc[mi][nj], ah[mi], bh0, bh1);
                    mma_bf16(acc[mi][nj], al[mi], bh0, bh1);
                    mma_bf16(acc[mi][nj], ah[mi], bl0, bl1);
                }
            }
        }
        __syncthreads();                      // compute done before buffer reuse
    }

    #pragma unroll
    for (int mi = 0; mi < 4; mi++) {
        #pragma unroll
        for (int nj = 0; nj < 4; nj++) {
            int r0 = m0 + warp_m * 64 + mi * 16 + gid;
            int c0 = n0 + warp_n * 32 + nj * 8 + 2 * tig;
            #pragma unroll
            for (int h = 0; h < 2; h++) {
                int row = r0 + h * 8;
                float v0 = acc[mi][nj][2 * h + 0] + bias[c0];
                float v1 = acc[mi][nj][2 * h + 1] + bias[c0 + 1];
                if (EPI == 1) {
                    v0 += resid[(size_t)row * N + c0];
                    v1 += resid[(size_t)row * N + c0 + 1];
                }
                if (EPI == 2) {
                    v0 = 0.5f * v0 * (1.0f + erff(v0 * 0.70710678118654752f));
                    v1 = 0.5f * v1 * (1.0f + erff(v1 * 0.70710678118654752f));
                    uint32_t hh = packbf(v0, v1);
                    size_t o = (size_t)row * (N >> 1) + (c0 >> 1);
                    Ch[o] = hh;
                    Cl[o] = packbf(v0 - bf_lo(hh), v1 - bf_hi(hh));
                } else {
                    float2 o; o.x = v0; o.y = v1;
                    *(float2*)(C + (size_t)row * N + c0) = o;
                }
            }
        }
    }
}

template<int EPI>
__global__ __launch_bounds__(256, 2)
void bmma_gemm(const uint32_t* __restrict__ Agh, const uint32_t* __restrict__ Agl,
               const uint32_t* __restrict__ Bgh, const uint32_t* __restrict__ Bgl,
               const float* __restrict__ bias, const float* __restrict__ resid,
               float* __restrict__ C, uint32_t* __restrict__ Ch, uint32_t* __restrict__ Cl,
               int N, int K)
{
    extern __shared__ uint32_t smx[];
    gemm_body<EPI>(Agh, Agl, Bgh, Bgl, bias, resid, C, Ch, Cl,
                   N, K, blockIdx.y * 128, blockIdx.x * 128, smx);
}

// Fused QKV: grid (18, 128)
__global__ __launch_bounds__(256, 2)
void qkv_gemm(const uint32_t* __restrict__ Agh, const uint32_t* __restrict__ Agl,
              const uint32_t* __restrict__ WqH, const uint32_t* __restrict__ WqL,
              const float* __restrict__ bq, float* __restrict__ q,
              const uint32_t* __restrict__ WkH, const uint32_t* __restrict__ WkL,
              const float* __restrict__ bk, float* __restrict__ k,
              const uint32_t* __restrict__ WvH, const uint32_t* __restrict__ WvL,
              const float* __restrict__ bv, float* __restrict__ v)
{
    extern __shared__ uint32_t smx[];
    const int sel = blockIdx.x / 6;
    const int n0 = (blockIdx.x % 6) * 128;
    const uint32_t* Bh = (sel == 0) ? WqH : (sel == 1) ? WkH : WvH;
    const uint32_t* Bl = (sel == 0) ? WqL : (sel == 1) ? WkL : WvL;
    const float* bias  = (sel == 0) ? bq  : (sel == 1) ? bk  : bv;
    float* C           = (sel == 0) ? q   : (sel == 1) ? k   : v;
    gemm_body<0>(Agh, Agl, Bh, Bl, bias, nullptr, C, nullptr, nullptr,
                 HID, HID, blockIdx.y * 128, n0, smx);
}

// ---------------- tensor-core flash attention (ping-pong SMEM) ----------
#define AST 76
#define BUFU (4*32*AST)
#define FATTN_SMEM ((2*BUFU + 128)*4)

__global__ __launch_bounds__(256, 1)
void fattn_kernel(const float* __restrict__ Q, const float* __restrict__ K,
                  const float* __restrict__ V, const float* __restrict__ mask,
                  uint32_t* __restrict__ ctxH, uint32_t* __restrict__ ctxL)
{
    extern __shared__ uint32_t dsm[];
    float* MsB = (float*)(dsm + 2 * BUFU);
    float* Qs = (float*)dsm;

    const int b = blockIdx.z, h = blockIdx.y, qt = blockIdx.x;
    const int tid = threadIdx.x;
    const int wid = tid >> 5, lane = tid & 31;
    const int gid = lane >> 2, tig = lane & 3;
    const size_t base = ((size_t)b * SEQ) * HID + h * DHD;

    int kkey[4], kc[4];
    const float* kptr[4];
    #pragma unroll
    for (int L = 0; L < 4; L++) {
        int p = tid + L * 256;
        kkey[L] = p & 63;
        kc[L] = ((p >> 6) & 15) * 4;
        kptr[L] = K + base + (size_t)kkey[L] * HID + kc[L];
    }
    int vkp[2], vc[2];
    const float* vptr[2];
    #pragma unroll
    for (int L = 0; L < 2; L++) {
        int p = tid + L * 256;
        vkp[L] = p & 31;
        vc[L] = ((p >> 5) & 15) * 4;
        vptr[L] = V + base + (size_t)(vkp[L] * 2) * HID + vc[L];
    }

    #pragma unroll
    for (int L = 0; L < 8; L++) {
        int p = tid + L * 256;
        int r = p >> 4;
        int c = (p & 15) * 4;
        *(float4*)&Qs[r * 68 + c] =
            *(const float4*)(Q + base + (size_t)(qt * 128 + r) * HID + c);
    }
    __syncthreads();

    uint32_t qh[4][4], ql[4][4];
    {
        const float* q0 = Qs + (wid * 16 + gid) * 68;
        const float* q8 = q0 + 8 * 68;
        #pragma unroll
        for (int s = 0; s < 4; s++) {
            float2 x0 = *(const float2*)(q0 + s * 16 + 2 * tig);
            float2 x1 = *(const float2*)(q8 + s * 16 + 2 * tig);
            float2 x2 = *(const float2*)(q0 + s * 16 + 8 + 2 * tig);
            float2 x3 = *(const float2*)(q8 + s * 16 + 8 + 2 * tig);
            qh[s][0] = packbf(x0.x, x0.y); ql[s][0] = packbf(x0.x - bf_lo(qh[s][0]), x0.y - bf_hi(qh[s][0]));
            qh[s][1] = packbf(x1.x, x1.y); ql[s][1] = packbf(x1.x - bf_lo(qh[s][1]), x1.y - bf_hi(qh[s][1]));
            qh[s][2] = packbf(x2.x, x2.y); ql[s][2] = packbf(x2.x - bf_lo(qh[s][2]), x2.y - bf_hi(qh[s][2]));
            qh[s][3] = packbf(x3.x, x3.y); ql[s][3] = packbf(x3.x - bf_lo(qh[s][3]), x3.y - bf_hi(qh[s][3]));
        }
    }

    float4 rk[4], rv0[2], rv1[2];
    float mreg = 1.0f;
    #pragma unroll
    for (int L = 0; L < 4; L++) rk[L] = *(const float4*)(kptr[L]);
    #pragma unroll
    for (int L = 0; L < 2; L++) {
        rv0[L] = *(const float4*)(vptr[L]);
        rv1[L] = *(const float4*)(vptr[L] + HID);
    }
    if (tid < 64) mreg = __ldg(&mask[b * SEQ + tid]);
    __syncthreads();

    float ctx[8][4];
    #pragma unroll
    for (int j = 0; j < 8; j++)
        #pragma unroll
        for (int r = 0; r < 4; r++) ctx[j][r] = 0.f;
    float m0 = -INFINITY, m1 = -INFINITY, l0 = 0.f, l1 = 0.f;

    const int NT = SEQ / 64;
    for (int kt = 0; kt < NT; kt++) {
        uint32_t* bf = dsm + (kt & 1) * BUFU;
        uint32_t* KH = bf;
        uint32_t* KL = bf + 32 * AST;
        uint32_t* VH = bf + 64 * AST;
        uint32_t* VL = bf + 96 * AST;
        float* Ms = MsB + (kt & 1) * 64;

        #pragma unroll
        for (int L = 0; L < 4; L++) {
            float4 v = rk[L];
            uint32_t h0 = packbf(v.x, v.y), h1 = packbf(v.z, v.w);
            uint32_t w0 = packbf(v.x - bf_lo(h0), v.y - bf_hi(h0));
            uint32_t w1 = packbf(v.z - bf_lo(h1), v.w - bf_hi(h1));
            int dp = kc[L] >> 1;
            KH[dp * AST + kkey[L]]       = h0;
            KH[(dp + 1) * AST + kkey[L]] = h1;
            KL[dp * AST + kkey[L]]       = w0;
            KL[(dp + 1) * AST + kkey[L]] = w1;
        }
        #pragma unroll
        for (int L = 0; L < 2; L++) {
            float4 f0 = rv0[L], f1 = rv1[L];
            uint32_t h0 = packbf(f0.x, f1.x), h1 = packbf(f0.y, f1.y);
            uint32_t h2 = packbf(f0.z, f1.z), h3 = packbf(f0.w, f1.w);
            uint32_t w0 = packbf(f0.x - bf_lo(h0), f1.x - bf_hi(h0));
            uint32_t w1 = packbf(f0.y - bf_lo(h1), f1.y - bf_hi(h1));
            uint32_t w2 = packbf(f0.z - bf_lo(h2), f1.z - bf_hi(h2));
            uint32_t w3 = packbf(f0.w - bf_lo(h3), f1.w - bf_hi(h3));
            uint4 hv; hv.x = h0; hv.y = h1; hv.z = h2; hv.w = h3;
            uint4 lv; lv.x = w0; lv.y = w1; lv.z = w2; lv.w = w3;
            *(uint4*)&VH[vkp[L] * AST + vc[L]] = hv;
            *(uint4*)&VL[vkp[L] * AST + vc[L]] = lv;
        }
        if (tid < 64)
            Ms[tid] = (1.0f - mreg) * -10000.0f;

        if (kt + 1 < NT) {
            const size_t off = (size_t)(kt + 1) * 64 * HID;
            #pragma unroll
            for (int L = 0; L < 4; L++) rk[L] = *(const float4*)(kptr[L] + off);
            #pragma unroll
            for (int L = 0; L < 2; L++) {
                rv0[L] = *(const float4*)(vptr[L] + off);
                rv1[L] = *(const float4*)(vptr[L] + off + HID);
            }
            if (tid < 64) mreg = __ldg(&mask[b * SEQ + (kt + 1) * 64 + tid]);
        }
        __syncthreads();

        float S[8][4];
        #pragma unroll
        for (int j = 0; j < 8; j++)
            #pragma unroll
            for (int r = 0; r < 4; r++) S[j][r] = 0.f;
        #pragma unroll
        for (int s = 0; s < 4; s++) {
            const uint32_t* kh = KH + (s * 8 + tig) * AST + gid;
            const uint32_t* kl = KL + (s * 8 + tig) * AST + gid;
            #pragma unroll
            for (int j = 0; j < 8; j++) {
                uint32_t bh0 = kh[j * 8], bh1 = kh[j * 8 + 4 * AST];
                uint32_t bl0 = kl[j * 8], bl1 = kl[j * 8 + 4 * AST];
                mma_bf16(S[j], qh[s], bh0, bh1);
                mma_bf16(S[j], ql[s], bh0, bh1);
                mma_bf16(S[j], qh[s], bl0, bl1);
            }
        }

        float mn0 = m0, mn1 = m1;
        #pragma unroll
        for (int j = 0; j < 8; j++) {
            float ms0 = Ms[j * 8 + 2 * tig], ms1 = Ms[j * 8 + 2 * tig + 1];
            S[j][0] = S[j][0] * 0.125f + ms0;
            S[j][1] = S[j][1] * 0.125f + ms1;
            S[j][2] = S[j][2] * 0.125f + ms0;
            S[j][3] = S[j][3] * 0.125f + ms1;
            mn0 = fmaxf(mn0, fmaxf(S[j][0], S[j][1]));
            mn1 = fmaxf(mn1, fmaxf(S[j][2], S[j][3]));
        }
        mn0 = fmaxf(mn0, __shfl_xor_sync(0xffffffffu, mn0, 1));
        mn0 = fmaxf(mn0, __shfl_xor_sync(0xffffffffu, mn0, 2));
        mn1 = fmaxf(mn1, __shfl_xor_sync(0xffffffffu, mn1, 1));
        mn1 = fmaxf(mn1, __shfl_xor_sync(0xffffffffu, mn1, 2));
        float alpha0 = __expf(m0 - mn0), alpha1 = __expf(m1 - mn1);
        l0 *= alpha0; l1 *= alpha1;
        #pragma unroll
        for (int j = 0; j < 8; j++) {
            ctx[j][0] *= alpha0; ctx[j][1] *= alpha0;
            ctx[j][2] *= alpha1; ctx[j][3] *= alpha1;
        }
        float ls0 = 0.f, ls1 = 0.f;
        uint32_t ph[8][2], pl[8][2];
        #pragma unroll
        for (int j = 0; j < 8; j++) {
            float e0 = __expf(S[j][0] - mn0);
            float e1 = __expf(S[j][1] - mn0);
            float e2 = __expf(S[j][2] - mn1);
            float e3 = __expf(S[j][3] - mn1);
            ls0 += e0 + e1; ls1 += e2 + e3;
            ph[j][0] = packbf(e0, e1);
            pl[j][0] = packbf(e0 - bf_lo(ph[j][0]), e1 - bf_hi(ph[j][0]));
            ph[j][1] = packbf(e2, e3);
            pl[j][1] = packbf(e2 - bf_lo(ph[j][1]), e3 - bf_hi(ph[j][1]));
        }
        ls0 += __shfl_xor_sync(0xffffffffu, ls0, 1);
        ls0 += __shfl_xor_sync(0xffffffffu, ls0, 2);
        ls1 += __shfl_xor_sync(0xffffffffu, ls1, 1);
        ls1 += __shfl_xor_sync(0xffffffffu, ls1, 2);
        l0 += ls0; l1 += ls1;
        m0 = mn0; m1 = mn1;

        #pragma unroll
        for (int s = 0; s < 4; s++) {
            uint32_t pa[4] = { ph[2 * s][0], ph[2 * s][1], ph[2 * s + 1][0], ph[2 * s + 1][1] };
            uint32_t pb[4] = { pl[2 * s][0], pl[2 * s][1], pl[2 * s + 1][0], pl[2 * s + 1][1] };
            const uint32_t* vh = VH + (s * 8 + tig) * AST + gid;
            const uint32_t* vl = VL + (s * 8 + tig) * AST + gid;
            #pragma unroll
            for (int j = 0; j < 8; j++) {
                uint32_t bh0 = vh[j * 8], bh1 = vh[j * 8 + 4 * AST];
                uint32_t bl0 = vl[j * 8], bl1 = vl[j * 8 + 4 * AST];
                mma_bf16(ctx[j], pa, bh0, bh1);
                mma_bf16(ctx[j], pb, bh0, bh1);
                mma_bf16(ctx[j], pa, bl0, bl1);
            }
        }
    }

    float inv0 = 1.0f / l0, inv1 = 1.0f / l1;
    int row0 = qt * 128 + wid * 16 + gid;
    size_t r0 = ((size_t)b * SEQ + row0) * HKP + h * 32 + tig;
    size_t r1 = r0 + 8 * HKP;
    #pragma unroll
    for (int j = 0; j < 8; j++) {
        float a0 = ctx[j][0] * inv0, a1 = ctx[j][1] * inv0;
        uint32_t hh = packbf(a0, a1);
        ctxH[r0 + j * 4] = hh;
        ctxL[r0 + j * 4] = packbf(a0 - bf_lo(hh), a1 - bf_hi(hh));
        float c0 = ctx[j][2] * inv1, c1 = ctx[j][3] * inv1;
        uint32_t hh1 = packbf(c0, c1);
        ctxH[r1 + j * 4] = hh1;
        ctxL[r1 + j * 4] = packbf(c0 - bf_lo(hh1), c1 - bf_hi(hh1));
    }
}

// ---------------- layernorm (plain) ----------------
__global__ __launch_bounds__(256)
void layernorm_kernel(const float* __restrict__ x, const float* __restrict__ g,
                      const float* __restrict__ b, float* __restrict__ y)
{
    __shared__ float red[8];
    const int row = blockIdx.x, t = threadIdx.x;
    const int warp = t >> 5, lane = t & 31;
    const float* xr = x + (size_t)row * HID;

    float v0 = xr[t], v1 = xr[t + 256], v2 = xr[t + 512];
    float s = v0 + v1 + v2;
    #pragma unroll
    for (int o = 16; o; o >>= 1) s += __shfl_xor_sync(0xffffffffu, s, o);
    if (lane == 0) red[warp] = s;
    __syncthreads();
    float tot = 0.f;
    #pragma unroll
    for (int i = 0; i < 8; i++) tot += red[i];
    float mean = tot * (1.0f / 768.0f);

    v0 -= mean; v1 -= mean; v2 -= mean;
    float ss = v0 * v0 + v1 * v1 + v2 * v2;
    #pragma unroll
    for (int o = 16; o; o >>= 1) ss += __shfl_xor_sync(0xffffffffu, ss, o);
    __syncthreads();
    if (lane == 0) red[warp] = ss;
    __syncthreads();
    tot = 0.f;
    #pragma unroll
    for (int i = 0; i < 8; i++) tot += red[i];
    float rstd = rsqrtf(tot * (1.0f / 768.0f) + 1e-12f);

    float* yr = y + (size_t)row * HID;
    yr[t]       = v0 * rstd * g[t]       + b[t];
    yr[t + 256] = v1 * rstd * g[t + 256] + b[t + 256];
    yr[t + 512] = v2 * rstd * g[t + 512] + b[t + 512];
}

// ---------------- layernorm + split emit ----------------
__global__ __launch_bounds__(384)
void layernorm_split_kernel(const float* __restrict__ x, const float* __restrict__ g,
                            const float* __restrict__ b, float* __restrict__ y,
                            uint32_t* __restrict__ yh, uint32_t* __restrict__ yl)
{
    __shared__ float red[12];
    const int row = blockIdx.x, t = threadIdx.x;
    const int warp = t >> 5, lane = t & 31;

    float2 v = ((const float2*)(x + (size_t)row * HID))[t];
    float s = v.x + v.y;
    #pragma unroll
    for (int o = 16; o; o >>= 1) s += __shfl_xor_sync(0xffffffffu, s, o);
    if (lane == 0) red[warp] = s;
    __syncthreads();
    float tot = 0.f;
    #pragma unroll
    for (int i = 0; i < 12; i++) tot += red[i];
    float mean = tot * (1.0f / 768.0f);

    float a0 = v.x - mean, a1 = v.y - mean;
    float ss = a0 * a0 + a1 * a1;
    #pragma unroll
    for (int o = 16; o; o >>= 1) ss += __shfl_xor_sync(0xffffffffu, ss, o);
    __syncthreads();
    if (lane == 0) red[warp] = ss;
    __syncthreads();
    tot = 0.f;
    #pragma unroll
    for (int i = 0; i < 12; i++) tot += red[i];
    float rstd = rsqrtf(tot * (1.0f / 768.0f) + 1e-12f);

    float2 gg = ((const float2*)g)[t];
    float2 bb = ((const float2*)b)[t];
    float p0 = a0 * rstd * gg.x + bb.x;
    float p1 = a1 * rstd * gg.y + bb.y;
    float2 o; o.x = p0; o.y = p1;
    ((float2*)(y + (size_t)row * HID))[t] = o;
    uint32_t hh = packbf(p0, p1);
    yh[(size_t)row * HKP + t] = hh;
    yl[(size_t)row * HKP + t] = packbf(p0 - bf_lo(hh), p1 - bf_hi(hh));
}

// ---------------- pooler head ----------------
__global__ void cls_kernel(const float* __restrict__ out, const float* __restrict__ Wc,
                           const float* __restrict__ bc, float* __restrict__ cls)
{
    int idx = blockIdx.x * blockDim.x + threadIdx.x;
    if (idx >= Bsz * HID) return;
    int m = idx / HID, n = idx % HID;
    const float* xr = out + (size_t)m * SEQ * HID;
    float s = 0.f;
    for (int k = 0; k < HID; k++) s += xr[k] * Wc[(size_t)k * HID + n];
    cls[idx] = tanhf(s + bc[n]);
}

__global__ void logits_kernel(const float* __restrict__ cls, const float* __restrict__ Wp,
                              const float* __restrict__ bp, float* __restrict__ logits)
{
    int idx = threadIdx.x;
    if (idx >= Bsz * 3) return;
    int m = idx / 3, n = idx % 3;
    float s = 0.f;
    for (int k = 0; k < HID; k++) s += cls[m * HID + k] * Wp[k * 3 + n];
    logits[idx] = s + bp[n];
}

// ---------------- launch ----------------
extern "C" void kernel_launch(void* const* d_in, const int* in_sizes, int n_in,
                              void* d_out, int out_size)
{
    const float* hidden = (const float*)d_in[0];
    const float* mask   = (const float*)d_in[1];
    const float* Wq = (const float*)d_in[2];  const float* bq = (const float*)d_in[3];
    const float* Wk = (const float*)d_in[4];  const float* bk = (const float*)d_in[5];
    const float* Wv = (const float*)d_in[6];  const float* bv = (const float*)d_in[7];
    const float* Wo = (const float*)d_in[8];  const float* bo = (const float*)d_in[9];
    const float* l1g = (const float*)d_in[10]; const float* l1b = (const float*)d_in[11];
    const float* W1 = (const float*)d_in[12]; const float* b1 = (const float*)d_in[13];
    const float* W2 = (const float*)d_in[14]; const float* b2 = (const float*)d_in[15];
    const float* l2g = (const float*)d_in[16]; const float* l2b = (const float*)d_in[17];
    const float* Wc = (const float*)d_in[18]; const float* bc = (const float*)d_in[19];
    const float* Wp = (const float*)d_in[20]; const float* bp = (const float*)d_in[21];

    float* out = (float*)d_out;
    float* logits = out + (size_t)Bsz * SEQ * HID;

    float *q, *k, *v, *attn, *tmp, *cls;
    cudaGetSymbolAddress((void**)&q,    g_q);
    cudaGetSymbolAddress((void**)&k,    g_k);
    cudaGetSymbolAddress((void**)&v,    g_v);
    cudaGetSymbolAddress((void**)&attn, g_attn);
    cudaGetSymbolAddress((void**)&tmp,  g_tmp);
    cudaGetSymbolAddress((void**)&cls,  g_cls);

    uint32_t *hidH,*hidL,*ctxH,*ctxL,*attnH,*attnL,*ffH,*ffL;
    uint32_t *WqH,*WqL,*WkH,*WkL,*WvH,*WvL,*WoH,*WoL,*W1H,*W1L,*W2H,*W2L;
    cudaGetSymbolAddress((void**)&hidH, g_hidH);   cudaGetSymbolAddress((void**)&hidL, g_hidL);
    cudaGetSymbolAddress((void**)&ctxH, g_ctxH);   cudaGetSymbolAddress((void**)&ctxL, g_ctxL);
    cudaGetSymbolAddress((void**)&attnH, g_attnH); cudaGetSymbolAddress((void**)&attnL, g_attnL);
    cudaGetSymbolAddress((void**)&ffH, g_ffH);     cudaGetSymbolAddress((void**)&ffL, g_ffL);
    cudaGetSymbolAddress((void**)&WqH, g_WqH);     cudaGetSymbolAddress((void**)&WqL, g_WqL);
    cudaGetSymbolAddress((void**)&WkH, g_WkH);     cudaGetSymbolAddress((void**)&WkL, g_WkL);
    cudaGetSymbolAddress((void**)&WvH, g_WvH);     cudaGetSymbolAddress((void**)&WvL, g_WvL);
    cudaGetSymbolAddress((void**)&WoH, g_WoH);     cudaGetSymbolAddress((void**)&WoL, g_WoL);
    cudaGetSymbolAddress((void**)&W1H, g_W1H);     cudaGetSymbolAddress((void**)&W1L, g_W1L);
    cudaGetSymbolAddress((void**)&W2H, g_W2H);     cudaGetSymbolAddress((void**)&W2L, g_W2L);

    cudaFuncSetAttribute(bmma_gemm<1>, cudaFuncAttributeMaxDynamicSharedMemorySize, GEMM_SMEM);
    cudaFuncSetAttribute(bmma_gemm<2>, cudaFuncAttributeMaxDynamicSharedMemorySize, GEMM_SMEM);
    cudaFuncSetAttribute(qkv_gemm,     cudaFuncAttributeMaxDynamicSharedMemorySize, GEMM_SMEM);
    cudaFuncSetAttribute(fattn_kernel, cudaFuncAttributeMaxDynamicSharedMemorySize, FATTN_SMEM);

    // ---- conversions ----
    size_t nHid = (size_t)MROWS * HKP;
    convA_kernel<<<(int)((nHid + 255) / 256), 256>>>(hidden, hidH, hidL, nHid);
    convB_kernel<<<(HKP * HID + 255) / 256, 256>>>(Wq, WqH, WqL, HKP, HID);
    convB_kernel<<<(HKP * HID + 255) / 256, 256>>>(Wk, WkH, WkL, HKP, HID);
    convB_kernel<<<(HKP * HID + 255) / 256, 256>>>(Wv, WvH, WvL, HKP, HID);
    convB_kernel<<<(HKP * HID + 255) / 256, 256>>>(Wo, WoH, WoL, HKP, HID);
    convB_kernel<<<(HKP * FFD + 255) / 256, 256>>>(W1, W1H, W1L, HKP, FFD);
    convB_kernel<<<(FKP * HID + 255) / 256, 256>>>(W2, W2H, W2L, FKP, HID);

    dim3 gH(HID / 128, MROWS / 128);     // (6,128)
    dim3 gF(FFD / 128, MROWS / 128);     // (24,128)

    qkv_gemm<<<dim3(18, MROWS / 128), 256, GEMM_SMEM>>>(
        hidH, hidL, WqH, WqL, bq, q, WkH, WkL, bk, k, WvH, WvL, bv, v);

    fattn_kernel<<<dim3(SEQ / 128, NHD, Bsz), 256, FATTN_SMEM>>>(q, k, v, mask, ctxH, ctxL);

    bmma_gemm<1><<<gH, 256, GEMM_SMEM>>>(ctxH, ctxL, WoH, WoL, bo, hidden, tmp, nullptr, nullptr, HID, HID);
    layernorm_split_kernel<<<MROWS, 384>>>(tmp, l1g, l1b, attn, attnH, attnL);

    bmma_gemm<2><<<gF, 256, GEMM_SMEM>>>(attnH, attnL, W1H, W1L, b1, nullptr, nullptr, ffH, ffL, FFD, HID);
    bmma_gemm<1><<<gH, 256, GEMM_SMEM>>>(ffH, ffL, W2H, W2L, b2, attn, tmp, nullptr, nullptr, HID, FFD);
    layernorm_kernel<<<MROWS, 256>>>(tmp, l2g, l2b, out);

    cls_kernel<<<(Bsz * HID + 255) / 256, 256>>>(out, Wc, bc, cls);
    logits_kernel<<<1, 64>>>(cls, Wp, bp, logits);
}

// round 16
// speedup vs baseline: 1.0935x; 1.0935x over previous
#include <cuda_runtime.h>
#include <math.h>
#include <stdint.h>

#define Bsz 16
#define SEQ 1024
#define HID 768
#define FFD 3072
#define NHD 12
#define DHD 64
#define MROWS (Bsz*SEQ)   // 16384
#define HKP (HID/2)       // 384
#define FKP (FFD/2)       // 1536

// ---------------- fp32 scratch ----------------
__device__ float g_q   [(size_t)MROWS*HID];
__device__ float g_k   [(size_t)MROWS*HID];
__device__ float g_v   [(size_t)MROWS*HID];
__device__ float g_attn[(size_t)MROWS*HID];
__device__ float g_tmp [(size_t)MROWS*HID];
__device__ float g_cls [(size_t)Bsz*HID];

// ---------------- split-bf16 scratch ----------------
__device__ uint32_t g_hidH [(size_t)MROWS*HKP];
__device__ uint32_t g_hidL [(size_t)MROWS*HKP];
__device__ uint32_t g_ctxH [(size_t)MROWS*HKP];
__device__ uint32_t g_ctxL [(size_t)MROWS*HKP];
__device__ uint32_t g_attnH[(size_t)MROWS*HKP];
__device__ uint32_t g_attnL[(size_t)MROWS*HKP];
__device__ uint32_t g_ffH  [(size_t)MROWS*FKP];
__device__ uint32_t g_ffL  [(size_t)MROWS*FKP];
__device__ uint32_t g_WqH[HKP*HID], g_WqL[HKP*HID];
__device__ uint32_t g_WkH[HKP*HID], g_WkL[HKP*HID];
__device__ uint32_t g_WvH[HKP*HID], g_WvL[HKP*HID];
__device__ uint32_t g_WoH[HKP*HID], g_WoL[HKP*HID];
__device__ uint32_t g_W1H[HKP*FFD], g_W1L[HKP*FFD];
__device__ uint32_t g_W2H[FKP*HID], g_W2L[FKP*HID];
// pre-split K/V planes for attention
__device__ uint32_t g_KsH[(size_t)Bsz*NHD*32*SEQ], g_KsL[(size_t)Bsz*NHD*32*SEQ];
__device__ uint32_t g_VsH[(size_t)Bsz*NHD*512*64], g_VsL[(size_t)Bsz*NHD*512*64];

// ---------------- bf16 split helpers ----------------
__device__ __forceinline__ uint32_t packbf(float lo, float hi) {
    uint32_t r;
    asm("cvt.rn.bf16x2.f32 %0, %1, %2;" : "=r"(r) : "f"(hi), "f"(lo));
    return r;
}
__device__ __forceinline__ float bf_lo(uint32_t u) { return __uint_as_float(u << 16); }
__device__ __forceinline__ float bf_hi(uint32_t u) { return __uint_as_float(u & 0xFFFF0000u); }

__device__ __forceinline__ void mma_bf16(float* c,
                                         const uint32_t* a, uint32_t b0, uint32_t b1)
{
    asm volatile(
        "mma.sync.aligned.m16n8k16.row.col.f32.bf16.bf16.f32 "
        "{%0,%1,%2,%3}, {%4,%5,%6,%7}, {%8,%9}, {%0,%1,%2,%3};\n"
        : "+f"(c[0]), "+f"(c[1]), "+f"(c[2]), "+f"(c[3])
        : "r"(a[0]), "r"(a[1]), "r"(a[2]), "r"(a[3]), "r"(b0), "r"(b1));
}

__device__ __forceinline__ void cp16(uint32_t sm, const void* g) {
    asm volatile("cp.async.cg.shared.global [%0], [%1], 16;" :: "r"(sm), "l"(g));
}

// ---------------- conversion pre-passes ----------------
__global__ void convA_kernel(const float* __restrict__ X,
                             uint32_t* __restrict__ Xh, uint32_t* __restrict__ Xl,
                             size_t n)
{
    size_t i = (size_t)blockIdx.x * blockDim.x + threadIdx.x;
    if (i >= n) return;
    float2 v = ((const float2*)X)[i];
    uint32_t h = packbf(v.x, v.y);
    Xh[i] = h;
    Xl[i] = packbf(v.x - bf_lo(h), v.y - bf_hi(h));
}

__global__ void convB_kernel(const float* __restrict__ W,
                             uint32_t* __restrict__ Wh, uint32_t* __restrict__ Wl,
                             int Kp, int N)
{
    int i = blockIdx.x * blockDim.x + threadIdx.x;
    if (i >= Kp * N) return;
    int kp = i / N, n = i % N;
    float a = W[(size_t)(2 * kp) * N + n];
    float b = W[(size_t)(2 * kp + 1) * N + n];
    uint32_t h = packbf(a, b);
    Wh[i] = h;
    Wl[i] = packbf(a - bf_lo(h), b - bf_hi(h));
}

// K split: Kf[token][HID] -> per (b,h): Ks[dp 0..31][key 0..SEQ-1], u32=pack(dh even,dh odd)
__global__ __launch_bounds__(256)
void ksplit_kernel(const float* __restrict__ Kf,
                   uint32_t* __restrict__ KsH, uint32_t* __restrict__ KsL)
{
    __shared__ uint32_t th[32][33];
    __shared__ uint32_t tl[32][33];
    const int kt = blockIdx.x, h = blockIdx.y, b = blockIdx.z;
    const int t = threadIdx.x;
    const int keyl = t >> 3;          // 0..31
    const int dq = t & 7;             // 0..7 -> 4 dp each
    const float* src = Kf + ((size_t)(b * SEQ) + kt * 32 + keyl) * HID + h * DHD + dq * 8;
    float4 v0 = *(const float4*)src;
    float4 v1 = *(const float4*)(src + 4);
    uint32_t h0 = packbf(v0.x, v0.y), h1 = packbf(v0.z, v0.w);
    uint32_t h2 = packbf(v1.x, v1.y), h3 = packbf(v1.z, v1.w);
    th[dq * 4 + 0][keyl] = h0; th[dq * 4 + 1][keyl] = h1;
    th[dq * 4 + 2][keyl] = h2; th[dq * 4 + 3][keyl] = h3;
    tl[dq * 4 + 0][keyl] = packbf(v0.x - bf_lo(h0), v0.y - bf_hi(h0));
    tl[dq * 4 + 1][keyl] = packbf(v0.z - bf_lo(h1), v0.w - bf_hi(h1));
    tl[dq * 4 + 2][keyl] = packbf(v1.x - bf_lo(h2), v1.y - bf_hi(h2));
    tl[dq * 4 + 3][keyl] = packbf(v1.z - bf_lo(h3), v1.w - bf_hi(h3));
    __syncthreads();
    const int dp = t >> 3;
    const int k0 = (t & 7) * 4;
    size_t o = ((size_t)(b * NHD + h) * 32 + dp) * SEQ + kt * 32 + k0;
    uint4 wh; wh.x = th[dp][k0]; wh.y = th[dp][k0 + 1]; wh.z = th[dp][k0 + 2]; wh.w = th[dp][k0 + 3];
    uint4 wl; wl.x = tl[dp][k0]; wl.y = tl[dp][k0 + 1]; wl.z = tl[dp][k0 + 2]; wl.w = tl[dp][k0 + 3];
    *(uint4*)(KsH + o) = wh;
    *(uint4*)(KsL + o) = wl;
}

// V split: Vf[token][HID] -> per (b,h): Vs[kp 0..511][dh 0..63], u32=pack(key even,key odd)
__global__ __launch_bounds__(256)
void vsplit_kernel(const float* __restrict__ Vf,
                   uint32_t* __restrict__ VsH, uint32_t* __restrict__ VsL)
{
    size_t i = (size_t)blockIdx.x * 256 + threadIdx.x;   // uint4 index
    int dq = (int)(i & 15);
    int kp = (int)((i >> 4) & 511);
    int bh = (int)(i >> 13);
    int h = bh % NHD, b = bh / NHD;
    const float* s0 = Vf + ((size_t)(b * SEQ) + 2 * kp) * HID + h * DHD + dq * 4;
    float4 f0 = *(const float4*)s0;
    float4 f1 = *(const float4*)(s0 + HID);
    uint32_t h0 = packbf(f0.x, f1.x), h1 = packbf(f0.y, f1.y);
    uint32_t h2 = packbf(f0.z, f1.z), h3 = packbf(f0.w, f1.w);
    uint4 wh; wh.x = h0; wh.y = h1; wh.z = h2; wh.w = h3;
    uint4 wl;
    wl.x = packbf(f0.x - bf_lo(h0), f1.x - bf_hi(h0));
    wl.y = packbf(f0.y - bf_lo(h1), f1.y - bf_hi(h1));
    wl.z = packbf(f0.z - bf_lo(h2), f1.z - bf_hi(h2));
    wl.w = packbf(f0.w - bf_lo(h3), f1.w - bf_hi(h3));
    ((uint4*)VsH)[i] = wh;
    ((uint4*)VsL)[i] = wl;
}

// ---------------- GEMM body: pre-split operands, cp.async 3-stage --------
#define ASTRIDE 20
#define BSTRIDE 136
#define APLANE (128*ASTRIDE)
#define BPLANE (16*BSTRIDE)
#define STAGEU (2*APLANE + 2*BPLANE)
#define GEMM_SMEM (3*STAGEU*4)

template<int EPI>
__device__ __forceinline__
void gemm_body(const uint32_t* __restrict__ Agh, const uint32_t* __restrict__ Agl,
               const uint32_t* __restrict__ Bgh, const uint32_t* __restrict__ Bgl,
               const float* __restrict__ bias, const float* __restrict__ resid,
               float* __restrict__ C, uint32_t* __restrict__ Ch, uint32_t* __restrict__ Cl,
               int N, int K, int m0, int n0, uint32_t* smx)
{
    const uint32_t smbase = (uint32_t)__cvta_generic_to_shared(smx);
    const int Kp = K >> 1;

    const int tid = threadIdx.x;
    const int wid = tid >> 5;
    const int lane = tid & 31;
    const int gid = lane >> 2;
    const int tig = lane & 3;
    const int warp_m = wid >> 2;
    const int warp_n = wid & 3;

    int am[2], ak[2], bk[2], bn[2];
    #pragma unroll
    for (int L = 0; L < 2; L++) {
        int c = tid + L * 256;
        am[L] = c >> 2;  ak[L] = (c & 3) * 4;
        bk[L] = c >> 5;  bn[L] = (c & 31) * 4;
    }

    auto issue = [&](int kt) {
        uint32_t st = smbase + (uint32_t)(kt % 3) * (STAGEU * 4);
        #pragma unroll
        for (int L = 0; L < 2; L++) {
            size_t ao = (size_t)(m0 + am[L]) * Kp + kt * 16 + ak[L];
            uint32_t ad = st + (am[L] * ASTRIDE + ak[L]) * 4;
            cp16(ad, Agh + ao);
            cp16(ad + APLANE * 4, Agl + ao);
            size_t bo = (size_t)(kt * 16 + bk[L]) * N + n0 + bn[L];
            uint32_t bd = st + (2 * APLANE + bk[L] * BSTRIDE + bn[L]) * 4;
            cp16(bd, Bgh + bo);
            cp16(bd + BPLANE * 4, Bgl + bo);
        }
        asm volatile("cp.async.commit_group;");
    };

    float acc[4][4][4];
    #pragma unroll
    for (int i = 0; i < 4; i++)
        #pragma unroll
        for (int j = 0; j < 4; j++)
            #pragma unroll
            for (int r = 0; r < 4; r++) acc[i][j][r] = 0.f;

    const int NT = K >> 5;
    issue(0);
    issue(1);

    for (int kt = 0; kt < NT; kt++) {
        if (kt + 1 < NT) asm volatile("cp.async.wait_group 1;");
        else             asm volatile("cp.async.wait_group 0;");
        __syncthreads();
        if (kt + 2 < NT) issue(kt + 2);

        const uint32_t* Sb = smx + (kt % 3) * STAGEU;
        const uint32_t* Bh_s = Sb + 2 * APLANE;
        const uint32_t* Bl_s = Bh_s + BPLANE;

        #pragma unroll
        for (int s = 0; s < 2; s++) {
            const uint32_t* pa = Sb + (warp_m * 64 + gid) * ASTRIDE + s * 8 + tig;
            const uint32_t* pl = pa + APLANE;

            uint32_t ah[4][4], al[4][4];
            #pragma unroll
            for (int mi = 0; mi < 4; mi++) {
                const uint32_t* qq = pa + mi * 16 * ASTRIDE;
                ah[mi][0] = qq[0];
                ah[mi][1] = qq[8 * ASTRIDE];
                ah[mi][2] = qq[4];
                ah[mi][3] = qq[8 * ASTRIDE + 4];
                const uint32_t* rr = pl + mi * 16 * ASTRIDE;
                al[mi][0] = rr[0];
                al[mi][1] = rr[8 * ASTRIDE];
                al[mi][2] = rr[4];
                al[mi][3] = rr[8 * ASTRIDE + 4];
            }
            const uint32_t* pb = Bh_s + (s * 8 + tig) * BSTRIDE + warp_n * 32 + gid;
            const uint32_t* pc = Bl_s + (s * 8 + tig) * BSTRIDE + warp_n * 32 + gid;
            #pragma unroll
            for (int nj = 0; nj < 4; nj++) {
                uint32_t bh0 = pb[nj * 8], bh1 = pb[nj * 8 + 4 * BSTRIDE];
                uint32_t bl0 = pc[nj * 8], bl1 = pc[nj * 8 + 4 * BSTRIDE];
                #pragma unroll
                for (int mi = 0; mi < 4; mi++) {
                    mma_bf16(acc[mi][nj], ah[mi], bh0, bh1);
                    mma_bf16(acc[mi][nj], al[mi], bh0, bh1);
                    mma_bf16(acc[mi][nj], ah[mi], bl0, bl1);
                }
            }
        }
        __syncthreads();
    }

    #pragma unroll
    for (int mi = 0; mi < 4; mi++) {
        #pragma unroll
        for (int nj = 0; nj < 4; nj++) {
            int r0 = m0 + warp_m * 64 + mi * 16 + gid;
            int c0 = n0 + warp_n * 32 + nj * 8 + 2 * tig;
            #pragma unroll
            for (int h = 0; h < 2; h++) {
                int row = r0 + h * 8;
                float v0 = acc[mi][nj][2 * h + 0] + bias[c0];
                float v1 = acc[mi][nj][2 * h + 1] + bias[c0 + 1];
                if (EPI == 1) {
                    v0 += resid[(size_t)row * N + c0];
                    v1 += resid[(size_t)row * N + c0 + 1];
                }
                if (EPI == 2) {
                    v0 = 0.5f * v0 * (1.0f + erff(v0 * 0.70710678118654752f));
                    v1 = 0.5f * v1 * (1.0f + erff(v1 * 0.70710678118654752f));
                    uint32_t hh = packbf(v0, v1);
                    size_t o = (size_t)row * (N >> 1) + (c0 >> 1);
                    Ch[o] = hh;
                    Cl[o] = packbf(v0 - bf_lo(hh), v1 - bf_hi(hh));
                } else {
                    float2 o; o.x = v0; o.y = v1;
                    *(float2*)(C + (size_t)row * N + c0) = o;
                }
            }
        }
    }
}

template<int EPI>
__global__ __launch_bounds__(256, 2)
void bmma_gemm(const uint32_t* __restrict__ Agh, const uint32_t* __restrict__ Agl,
               const uint32_t* __restrict__ Bgh, const uint32_t* __restrict__ Bgl,
               const float* __restrict__ bias, const float* __restrict__ resid,
               float* __restrict__ C, uint32_t* __restrict__ Ch, uint32_t* __restrict__ Cl,
               int N, int K)
{
    extern __shared__ uint32_t smx[];
    gemm_body<EPI>(Agh, Agl, Bgh, Bgl, bias, resid, C, Ch, Cl,
                   N, K, blockIdx.y * 128, blockIdx.x * 128, smx);
}

__global__ __launch_bounds__(256, 2)
void qkv_gemm(const uint32_t* __restrict__ Agh, const uint32_t* __restrict__ Agl,
              const uint32_t* __restrict__ WqH, const uint32_t* __restrict__ WqL,
              const float* __restrict__ bq, float* __restrict__ q,
              const uint32_t* __restrict__ WkH, const uint32_t* __restrict__ WkL,
              const float* __restrict__ bk, float* __restrict__ k,
              const uint32_t* __restrict__ WvH, const uint32_t* __restrict__ WvL,
              const float* __restrict__ bv, float* __restrict__ v)
{
    extern __shared__ uint32_t smx[];
    const int sel = blockIdx.x / 6;
    const int n0 = (blockIdx.x % 6) * 128;
    const uint32_t* Bh = (sel == 0) ? WqH : (sel == 1) ? WkH : WvH;
    const uint32_t* Bl = (sel == 0) ? WqL : (sel == 1) ? WkL : WvL;
    const float* bias  = (sel == 0) ? bq  : (sel == 1) ? bk  : bv;
    float* C           = (sel == 0) ? q   : (sel == 1) ? k   : v;
    gemm_body<0>(Agh, Agl, Bh, Bl, bias, nullptr, C, nullptr, nullptr,
                 HID, HID, blockIdx.y * 128, n0, smx);
}

// ---------------- flash attention: pre-split K/V, cp.async ping-pong ----
#define AST 76
#define BUFU (4*32*AST)                 // u32 per buffer (9728)
#define FATTN_SMEM (2*BUFU*4 + 512)

__global__ __launch_bounds__(256, 2)
void fattn_kernel(const float* __restrict__ Q,
                  const uint32_t* __restrict__ KsH, const uint32_t* __restrict__ KsL,
                  const uint32_t* __restrict__ VsH, const uint32_t* __restrict__ VsL,
                  const float* __restrict__ mask,
                  uint32_t* __restrict__ ctxH, uint32_t* __restrict__ ctxL)
{
    extern __shared__ uint32_t dsm[];
    float* MsB = (float*)(dsm + 2 * BUFU);   // [2][64]
    float* Qs = (float*)dsm;                 // prologue overlay (34.8KB < buf 38.9KB)

    const int b = blockIdx.z, h = blockIdx.y, qt = blockIdx.x;
    const int tid = threadIdx.x;
    const int wid = tid >> 5, lane = tid & 31;
    const int gid = lane >> 2, tig = lane & 3;
    const int bh = b * NHD + h;
    const uint32_t smbase = (uint32_t)__cvta_generic_to_shared(dsm);

    // cp.async chunk geometry: 2 chunks x 4 planes per thread
    int cr[2], cj[2];
    #pragma unroll
    for (int L = 0; L < 2; L++) {
        int c = tid + L * 256;
        cr[L] = c >> 4;          // row 0..31
        cj[L] = c & 15;          // 16B chunk within 256B row
    }

    auto issue = [&](int kt) {
        uint32_t st = smbase + (uint32_t)(kt & 1) * (BUFU * 4);
        #pragma unroll
        for (int L = 0; L < 2; L++) {
            uint32_t dst = st + cr[L] * (AST * 4) + cj[L] * 16;
            size_t ks = ((size_t)bh * 32 + cr[L]) * SEQ + kt * 64 + cj[L] * 4;
            cp16(dst,                  KsH + ks);
            cp16(dst + 32 * AST * 4,   KsL + ks);
            size_t vs = ((size_t)bh * 512 + kt * 32 + cr[L]) * 64 + cj[L] * 4;
            cp16(dst + 64 * AST * 4,   VsH + vs);
            cp16(dst + 96 * AST * 4,   VsL + vs);
        }
        asm volatile("cp.async.commit_group;");
    };

    // ---- stage Q tile, build fragments ----
    const size_t qbase = ((size_t)b * SEQ) * HID + h * DHD;
    #pragma unroll
    for (int L = 0; L < 8; L++) {
        int p = tid + L * 256;
        int r = p >> 4;
        int c = (p & 15) * 4;
        *(float4*)&Qs[r * 68 + c] =
            *(const float4*)(Q + qbase + (size_t)(qt * 128 + r) * HID + c);
    }
    __syncthreads();

    uint32_t qh[4][4], ql[4][4];
    {
        const float* q0 = Qs + (wid * 16 + gid) * 68;
        const float* q8 = q0 + 8 * 68;
        #pragma unroll
        for (int s = 0; s < 4; s++) {
            float2 x0 = *(const float2*)(q0 + s * 16 + 2 * tig);
            float2 x1 = *(const float2*)(q8 + s * 16 + 2 * tig);
            float2 x2 = *(const float2*)(q0 + s * 16 + 8 + 2 * tig);
            float2 x3 = *(const float2*)(q8 + s * 16 + 8 + 2 * tig);
            qh[s][0] = packbf(x0.x, x0.y); ql[s][0] = packbf(x0.x - bf_lo(qh[s][0]), x0.y - bf_hi(qh[s][0]));
            qh[s][1] = packbf(x1.x, x1.y); ql[s][1] = packbf(x1.x - bf_lo(qh[s][1]), x1.y - bf_hi(qh[s][1]));
            qh[s][2] = packbf(x2.x, x2.y); ql[s][2] = packbf(x2.x - bf_lo(qh[s][2]), x2.y - bf_hi(qh[s][2]));
            qh[s][3] = packbf(x3.x, x3.y); ql[s][3] = packbf(x3.x - bf_lo(qh[s][3]), x3.y - bf_hi(qh[s][3]));
        }
    }
    float mreg = 1.0f;
    if (tid < 64) mreg = __ldg(&mask[b * SEQ + tid]);
    __syncthreads();          // Qs reads done before buffer 0 overwrite

    issue(0);

    float ctx[8][4];
    #pragma unroll
    for (int j = 0; j < 8; j++)
        #pragma unroll
        for (int r = 0; r < 4; r++) ctx[j][r] = 0.f;
    float m0 = -INFINITY, m1 = -INFINITY, l0 = 0.f, l1 = 0.f;

    const int NT = SEQ / 64;
    for (int kt = 0; kt < NT; kt++) {
        asm volatile("cp.async.wait_group 0;");
        if (tid < 64)
            MsB[(kt & 1) * 64 + tid] = (1.0f - mreg) * -10000.0f;
        if (kt + 1 < NT && tid < 64)
            mreg = __ldg(&mask[b * SEQ + (kt + 1) * 64 + tid]);
        __syncthreads();      // tile kt visible; prior compute on other buffer done
        if (kt + 1 < NT) issue(kt + 1);

        const uint32_t* bf = dsm + (kt & 1) * BUFU;
        const uint32_t* KH = bf;
        const uint32_t* KL = bf + 32 * AST;
        const uint32_t* VH = bf + 64 * AST;
        const uint32_t* VL = bf + 96 * AST;
        const float* Ms = MsB + (kt & 1) * 64;

        // ---- S = Q K^T ----
        float S[8][4];
        #pragma unroll
        for (int j = 0; j < 8; j++)
            #pragma unroll
            for (int r = 0; r < 4; r++) S[j][r] = 0.f;
        #pragma unroll
        for (int s = 0; s < 4; s++) {
            const uint32_t* kh = KH + (s * 8 + tig) * AST + gid;
            const uint32_t* kl = KL + (s * 8 + tig) * AST + gid;
            #pragma unroll
            for (int j = 0; j < 8; j++) {
                uint32_t bh0 = kh[j * 8], bh1 = kh[j * 8 + 4 * AST];
                uint32_t bl0 = kl[j * 8], bl1 = kl[j * 8 + 4 * AST];
                mma_bf16(S[j], qh[s], bh0, bh1);
                mma_bf16(S[j], ql[s], bh0, bh1);
                mma_bf16(S[j], qh[s], bl0, bl1);
            }
        }

        // ---- mask + scale + online softmax (e kept in S) ----
        float mn0 = m0, mn1 = m1;
        #pragma unroll
        for (int j = 0; j < 8; j++) {
            float ms0 = Ms[j * 8 + 2 * tig], ms1 = Ms[j * 8 + 2 * tig + 1];
            S[j][0] = S[j][0] * 0.125f + ms0;
            S[j][1] = S[j][1] * 0.125f + ms1;
            S[j][2] = S[j][2] * 0.125f + ms0;
            S[j][3] = S[j][3] * 0.125f + ms1;
            mn0 = fmaxf(mn0, fmaxf(S[j][0], S[j][1]));
            mn1 = fmaxf(mn1, fmaxf(S[j][2], S[j][3]));
        }
        mn0 = fmaxf(mn0, __shfl_xor_sync(0xffffffffu, mn0, 1));
        mn0 = fmaxf(mn0, __shfl_xor_sync(0xffffffffu, mn0, 2));
        mn1 = fmaxf(mn1, __shfl_xor_sync(0xffffffffu, mn1, 1));
        mn1 = fmaxf(mn1, __shfl_xor_sync(0xffffffffu, mn1, 2));
        float alpha0 = __expf(m0 - mn0), alpha1 = __expf(m1 - mn1);
        l0 *= alpha0; l1 *= alpha1;
        #pragma unroll
        for (int j = 0; j < 8; j++) {
            ctx[j][0] *= alpha0; ctx[j][1] *= alpha0;
            ctx[j][2] *= alpha1; ctx[j][3] *= alpha1;
        }
        float ls0 = 0.f, ls1 = 0.f;
        #pragma unroll
        for (int j = 0; j < 8; j++) {
            S[j][0] = __expf(S[j][0] - mn0);
            S[j][1] = __expf(S[j][1] - mn0);
            S[j][2] = __expf(S[j][2] - mn1);
            S[j][3] = __expf(S[j][3] - mn1);
            ls0 += S[j][0] + S[j][1];
            ls1 += S[j][2] + S[j][3];
        }
        ls0 += __shfl_xor_sync(0xffffffffu, ls0, 1);
        ls0 += __shfl_xor_sync(0xffffffffu, ls0, 2);
        ls1 += __shfl_xor_sync(0xffffffffu, ls1, 1);
        ls1 += __shfl_xor_sync(0xffffffffu, ls1, 2);
        l0 += ls0; l1 += ls1;
        m0 = mn0; m1 = mn1;

        // ---- ctx += P V (P packed on the fly from S) ----
        #pragma unroll
        for (int s = 0; s < 4; s++) {
            uint32_t pa[4], pb[4];
            pa[0] = packbf(S[2 * s][0], S[2 * s][1]);
            pa[1] = packbf(S[2 * s][2], S[2 * s][3]);
            pa[2] = packbf(S[2 * s + 1][0], S[2 * s + 1][1]);
            pa[3] = packbf(S[2 * s + 1][2], S[2 * s + 1][3]);
            pb[0] = packbf(S[2 * s][0] - bf_lo(pa[0]), S[2 * s][1] - bf_hi(pa[0]));
            pb[1] = packbf(S[2 * s][2] - bf_lo(pa[1]), S[2 * s][3] - bf_hi(pa[1]));
            pb[2] = packbf(S[2 * s + 1][0] - bf_lo(pa[2]), S[2 * s + 1][1] - bf_hi(pa[2]));
            pb[3] = packbf(S[2 * s + 1][2] - bf_lo(pa[3]), S[2 * s + 1][3] - bf_hi(pa[3]));
            const uint32_t* vh = VH + (s * 8 + tig) * AST + gid;
            const uint32_t* vl = VL + (s * 8 + tig) * AST + gid;
            #pragma unroll
            for (int j = 0; j < 8; j++) {
                uint32_t bh0 = vh[j * 8], bh1 = vh[j * 8 + 4 * AST];
                uint32_t bl0 = vl[j * 8], bl1 = vl[j * 8 + 4 * AST];
                mma_bf16(ctx[j], pa, bh0, bh1);
                mma_bf16(ctx[j], pb, bh0, bh1);
                mma_bf16(ctx[j], pa, bl0, bl1);
            }
        }
    }

    // ---- epilogue: normalize + emit split planes ----
    float inv0 = 1.0f / l0, inv1 = 1.0f / l1;
    int row0 = qt * 128 + wid * 16 + gid;
    size_t r0 = ((size_t)b * SEQ + row0) * HKP + h * 32 + tig;
    size_t r1 = r0 + 8 * HKP;
    #pragma unroll
    for (int j = 0; j < 8; j++) {
        float a0 = ctx[j][0] * inv0, a1 = ctx[j][1] * inv0;
        uint32_t hh = packbf(a0, a1);
        ctxH[r0 + j * 4] = hh;
        ctxL[r0 + j * 4] = packbf(a0 - bf_lo(hh), a1 - bf_hi(hh));
        float c0 = ctx[j][2] * inv1, c1 = ctx[j][3] * inv1;
        uint32_t hh1 = packbf(c0, c1);
        ctxH[r1 + j * 4] = hh1;
        ctxL[r1 + j * 4] = packbf(c0 - bf_lo(hh1), c1 - bf_hi(hh1));
    }
}

// ---------------- layernorm (plain) ----------------
__global__ __launch_bounds__(256)
void layernorm_kernel(const float* __restrict__ x, const float* __restrict__ g,
                      const float* __restrict__ b, float* __restrict__ y)
{
    __shared__ float red[8];
    const int row = blockIdx.x, t = threadIdx.x;
    const int warp = t >> 5, lane = t & 31;
    const float* xr = x + (size_t)row * HID;

    float v0 = xr[t], v1 = xr[t + 256], v2 = xr[t + 512];
    float s = v0 + v1 + v2;
    #pragma unroll
    for (int o = 16; o; o >>= 1) s += __shfl_xor_sync(0xffffffffu, s, o);
    if (lane == 0) red[warp] = s;
    __syncthreads();
    float tot = 0.f;
    #pragma unroll
    for (int i = 0; i < 8; i++) tot += red[i];
    float mean = tot * (1.0f / 768.0f);

    v0 -= mean; v1 -= mean; v2 -= mean;
    float ss = v0 * v0 + v1 * v1 + v2 * v2;
    #pragma unroll
    for (int o = 16; o; o >>= 1) ss += __shfl_xor_sync(0xffffffffu, ss, o);
    __syncthreads();
    if (lane == 0) red[warp] = ss;
    __syncthreads();
    tot = 0.f;
    #pragma unroll
    for (int i = 0; i < 8; i++) tot += red[i];
    float rstd = rsqrtf(tot * (1.0f / 768.0f) + 1e-12f);

    float* yr = y + (size_t)row * HID;
    yr[t]       = v0 * rstd * g[t]       + b[t];
    yr[t + 256] = v1 * rstd * g[t + 256] + b[t + 256];
    yr[t + 512] = v2 * rstd * g[t + 512] + b[t + 512];
}

// ---------------- layernorm + split emit ----------------
__global__ __launch_bounds__(384)
void layernorm_split_kernel(const float* __restrict__ x, const float* __restrict__ g,
                            const float* __restrict__ b, float* __restrict__ y,
                            uint32_t* __restrict__ yh, uint32_t* __restrict__ yl)
{
    __shared__ float red[12];
    const int row = blockIdx.x, t = threadIdx.x;
    const int warp = t >> 5, lane = t & 31;

    float2 v = ((const float2*)(x + (size_t)row * HID))[t];
    float s = v.x + v.y;
    #pragma unroll
    for (int o = 16; o; o >>= 1) s += __shfl_xor_sync(0xffffffffu, s, o);
    if (lane == 0) red[warp] = s;
    __syncthreads();
    float tot = 0.f;
    #pragma unroll
    for (int i = 0; i < 12; i++) tot += red[i];
    float mean = tot * (1.0f / 768.0f);

    float a0 = v.x - mean, a1 = v.y - mean;
    float ss = a0 * a0 + a1 * a1;
    #pragma unroll
    for (int o = 16; o; o >>= 1) ss += __shfl_xor_sync(0xffffffffu, ss, o);
    __syncthreads();
    if (lane == 0) red[warp] = ss;
    __syncthreads();
    tot = 0.f;
    #pragma unroll
    for (int i = 0; i < 12; i++) tot += red[i];
    float rstd = rsqrtf(tot * (1.0f / 768.0f) + 1e-12f);

    float2 gg = ((const float2*)g)[t];
    float2 bb = ((const float2*)b)[t];
    float p0 = a0 * rstd * gg.x + bb.x;
    float p1 = a1 * rstd * gg.y + bb.y;
    float2 o; o.x = p0; o.y = p1;
    ((float2*)(y + (size_t)row * HID))[t] = o;
    uint32_t hh = packbf(p0, p1);
    yh[(size_t)row * HKP + t] = hh;
    yl[(size_t)row * HKP + t] = packbf(p0 - bf_lo(hh), p1 - bf_hi(hh));
}

// ---------------- pooler head ----------------
__global__ void cls_kernel(const float* __restrict__ out, const float* __restrict__ Wc,
                           const float* __restrict__ bc, float* __restrict__ cls)
{
    int idx = blockIdx.x * blockDim.x + threadIdx.x;
    if (idx >= Bsz * HID) return;
    int m = idx / HID, n = idx % HID;
    const float* xr = out + (size_t)m * SEQ * HID;
    float s = 0.f;
    for (int k = 0; k < HID; k++) s += xr[k] * Wc[(size_t)k * HID + n];
    cls[idx] = tanhf(s + bc[n]);
}

__global__ void logits_kernel(const float* __restrict__ cls, const float* __restrict__ Wp,
                              const float* __restrict__ bp, float* __restrict__ logits)
{
    int idx = threadIdx.x;
    if (idx >= Bsz * 3) return;
    int m = idx / 3, n = idx % 3;
    float s = 0.f;
    for (int k = 0; k < HID; k++) s += cls[m * HID + k] * Wp[k * 3 + n];
    logits[idx] = s + bp[n];
}

// ---------------- launch ----------------
extern "C" void kernel_launch(void* const* d_in, const int* in_sizes, int n_in,
                              void* d_out, int out_size)
{
    const float* hidden = (const float*)d_in[0];
    const float* mask   = (const float*)d_in[1];
    const float* Wq = (const float*)d_in[2];  const float* bq = (const float*)d_in[3];
    const float* Wk = (const float*)d_in[4];  const float* bk = (const float*)d_in[5];
    const float* Wv = (const float*)d_in[6];  const float* bv = (const float*)d_in[7];
    const float* Wo = (const float*)d_in[8];  const float* bo = (const float*)d_in[9];
    const float* l1g = (const float*)d_in[10]; const float* l1b = (const float*)d_in[11];
    const float* W1 = (const float*)d_in[12]; const float* b1 = (const float*)d_in[13];
    const float* W2 = (const float*)d_in[14]; const float* b2 = (const float*)d_in[15];
    const float* l2g = (const float*)d_in[16]; const float* l2b = (const float*)d_in[17];
    const float* Wc = (const float*)d_in[18]; const float* bc = (const float*)d_in[19];
    const float* Wp = (const float*)d_in[20]; const float* bp = (const float*)d_in[21];

    float* out = (float*)d_out;
    float* logits = out + (size_t)Bsz * SEQ * HID;

    float *q, *k, *v, *attn, *tmp, *cls;
    cudaGetSymbolAddress((void**)&q,    g_q);
    cudaGetSymbolAddress((void**)&k,    g_k);
    cudaGetSymbolAddress((void**)&v,    g_v);
    cudaGetSymbolAddress((void**)&attn, g_attn);
    cudaGetSymbolAddress((void**)&tmp,  g_tmp);
    cudaGetSymbolAddress((void**)&cls,  g_cls);

    uint32_t *hidH,*hidL,*ctxH,*ctxL,*attnH,*attnL,*ffH,*ffL;
    uint32_t *WqH,*WqL,*WkH,*WkL,*WvH,*WvL,*WoH,*WoL,*W1H,*W1L,*W2H,*W2L;
    uint32_t *KsH,*KsL,*VsH,*VsL;
    cudaGetSymbolAddress((void**)&hidH, g_hidH);   cudaGetSymbolAddress((void**)&hidL, g_hidL);
    cudaGetSymbolAddress((void**)&ctxH, g_ctxH);   cudaGetSymbolAddress((void**)&ctxL, g_ctxL);
    cudaGetSymbolAddress((void**)&attnH, g_attnH); cudaGetSymbolAddress((void**)&attnL, g_attnL);
    cudaGetSymbolAddress((void**)&ffH, g_ffH);     cudaGetSymbolAddress((void**)&ffL, g_ffL);
    cudaGetSymbolAddress((void**)&WqH, g_WqH);     cudaGetSymbolAddress((void**)&WqL, g_WqL);
    cudaGetSymbolAddress((void**)&WkH, g_WkH);     cudaGetSymbolAddress((void**)&WkL, g_WkL);
    cudaGetSymbolAddress((void**)&WvH, g_WvH);     cudaGetSymbolAddress((void**)&WvL, g_WvL);
    cudaGetSymbolAddress((void**)&WoH, g_WoH);     cudaGetSymbolAddress((void**)&WoL, g_WoL);
    cudaGetSymbolAddress((void**)&W1H, g_W1H);     cudaGetSymbolAddress((void**)&W1L, g_W1L);
    cudaGetSymbolAddress((void**)&W2H, g_W2H);     cudaGetSymbolAddress((void**)&W2L, g_W2L);
    cudaGetSymbolAddress((void**)&KsH, g_KsH);     cudaGetSymbolAddress((void**)&KsL, g_KsL);
    cudaGetSymbolAddress((void**)&VsH, g_VsH);     cudaGetSymbolAddress((void**)&VsL, g_VsL);

    cudaFuncSetAttribute(bmma_gemm<1>, cudaFuncAttributeMaxDynamicSharedMemorySize, GEMM_SMEM);
    cudaFuncSetAttribute(bmma_gemm<2>, cudaFuncAttributeMaxDynamicSharedMemorySize, GEMM_SMEM);
    cudaFuncSetAttribute(qkv_gemm,     cudaFuncAttributeMaxDynamicSharedMemorySize, GEMM_SMEM);
    cudaFuncSetAttribute(fattn_kernel, cudaFuncAttributeMaxDynamicSharedMemorySize, FATTN_SMEM);

    // ---- conversions ----
    size_t nHid = (size_t)MROWS * HKP;
    convA_kernel<<<(int)((nHid + 255) / 256), 256>>>(hidden, hidH, hidL, nHid);
    convB_kernel<<<(HKP * HID + 255) / 256, 256>>>(Wq, WqH, WqL, HKP, HID);
    convB_kernel<<<(HKP * HID + 255) / 256, 256>>>(Wk, WkH, WkL, HKP, HID);
    convB_kernel<<<(HKP * HID + 255) / 256, 256>>>(Wv, WvH, WvL, HKP, HID);
    convB_kernel<<<(HKP * HID + 255) / 256, 256>>>(Wo, WoH, WoL, HKP, HID);
    convB_kernel<<<(HKP * FFD + 255) / 256, 256>>>(W1, W1H, W1L, HKP, FFD);
    convB_kernel<<<(FKP * HID + 255) / 256, 256>>>(W2, W2H, W2L, FKP, HID);

    dim3 gH(HID / 128, MROWS / 128);     // (6,128)
    dim3 gF(FFD / 128, MROWS / 128);     // (24,128)

    qkv_gemm<<<dim3(18, MROWS / 128), 256, GEMM_SMEM>>>(
        hidH, hidL, WqH, WqL, bq, q, WkH, WkL, bk, k, WvH, WvL, bv, v);

    ksplit_kernel<<<dim3(SEQ / 32, NHD, Bsz), 256>>>(k, KsH, KsL);
    vsplit_kernel<<<(Bsz * NHD * 512 * 64 / 4) / 256, 256>>>(v, VsH, VsL);

    fattn_kernel<<<dim3(SEQ / 128, NHD, Bsz), 256, FATTN_SMEM>>>(
        q, KsH, KsL, VsH, VsL, mask, ctxH, ctxL);

    bmma_gemm<1><<<gH, 256, GEMM_SMEM>>>(ctxH, ctxL, WoH, WoL, bo, hidden, tmp, nullptr, nullptr, HID, HID);
    layernorm_split_kernel<<<MROWS, 384>>>(tmp, l1g, l1b, attn, attnH, attnL);

    bmma_gemm<2><<<gF, 256, GEMM_SMEM>>>(attnH, attnL, W1H, W1L, b1, nullptr, nullptr, ffH, ffL, FFD, HID);
    bmma_gemm<1><<<gH, 256, GEMM_SMEM>>>(ffH, ffL, W2H, W2L, b2, attn, tmp, nullptr, nullptr, HID, FFD);
    layernorm_kernel<<<MROWS, 256>>>(tmp, l2g, l2b, out);

    cls_kernel<<<(Bsz * HID + 255) / 256, 256>>>(out, Wc, bc, cls);
    logits_kernel<<<1, 64>>>(cls, Wp, bp, logits);
}